// round 7
// baseline (speedup 1.0000x reference)
#include <cuda_runtime.h>
#include <cuda_bf16.h>

// query [TOTAL,16,128] f32, key/value [TOTAL,4,128] f32, q_start_loc [B] i32,
// q_seqlens [B] i32 -> out [TOTAL,16,128] f32.
#define HEADS   16
#define KVHEADS 4
#define DHEAD   128
#define WINDOW  1024
#define BQ 128
#define BK 64
#define NTHREADS 320          // 8 consumer warps + 2 producer warps

#define SCALE_OVER_CAP 0.0029462782549439484f   // (128^-0.5)/30
#define TWO_LOG2E 2.8853900817779268f
#define CAP_LOG2E 43.2808512266689f             // 30*log2(e)

// smem: bf16 tiles, rows of 128 bf16 (256B = 16 chunks of 16B), chunk-XOR swizzle.
#define QH_OFF 0          // [128][128] bf16 : 32768
#define QL_OFF 32768
#define KV_BASE 65536     // two 64KB buffers: {KH,KL,VH,VL} each 16384
#define KVBUF   65536
#define KH_R 0
#define KL_R 16384
#define VH_R 32768
#define VL_R 49152
#define SMEM_TOTAL 196608

#define BAR_FULL0 1
#define BAR_FULL1 2
#define BAR_EMPTY0 3
#define BAR_EMPTY1 4
#define BAR_SYNC(id)   asm volatile("bar.sync %0, %1;"   :: "r"(id), "r"(NTHREADS) : "memory")
#define BAR_ARRIVE(id) asm volatile("bar.arrive %0, %1;" :: "r"(id), "r"(NTHREADS) : "memory")

typedef unsigned int u32;
typedef unsigned short u16;

static __device__ __forceinline__ u32 smem_u32(const void* p) {
    u32 a;
    asm("{ .reg .u64 t; cvta.to.shared.u64 t, %1; cvt.u32.u64 %0, t; }"
        : "=r"(a) : "l"(p));
    return a;
}
static __device__ __forceinline__ u32 swadr(int row, int chunk) {
    return (u32)((row << 8) + ((chunk ^ (row & 7)) << 4));
}
static __device__ __forceinline__ void ldsm4(u32 addr, u32 r[4]) {
    asm volatile("ldmatrix.sync.aligned.m8n8.x4.shared.b16 {%0,%1,%2,%3}, [%4];"
        : "=r"(r[0]), "=r"(r[1]), "=r"(r[2]), "=r"(r[3]) : "r"(addr));
}
static __device__ __forceinline__ void ldsm4t(u32 addr, u32 r[4]) {
    asm volatile("ldmatrix.sync.aligned.m8n8.x4.trans.shared.b16 {%0,%1,%2,%3}, [%4];"
        : "=r"(r[0]), "=r"(r[1]), "=r"(r[2]), "=r"(r[3]) : "r"(addr));
}
static __device__ __forceinline__ void mma_bf16(float c[4], const u32 a[4], const u32 b[2]) {
    asm volatile(
        "mma.sync.aligned.m16n8k16.row.col.f32.bf16.bf16.f32 "
        "{%0,%1,%2,%3}, {%4,%5,%6,%7}, {%8,%9}, {%0,%1,%2,%3};"
        : "+f"(c[0]), "+f"(c[1]), "+f"(c[2]), "+f"(c[3])
        : "r"(a[0]), "r"(a[1]), "r"(a[2]), "r"(a[3]), "r"(b[0]), "r"(b[1]));
}

// split (x0,x1) into packed bf16x2 hi and lo parts; low half = x0.
static __device__ __forceinline__ void splitpair(float x0, float x1, u32& hp, u32& lp) {
    u32 hpk;
    asm("cvt.rn.bf16x2.f32 %0, %1, %2;" : "=r"(hpk) : "f"(x1), "f"(x0));
    u32 f0, f1;
    asm("prmt.b32 %0, %1, 0, 0x1044;" : "=r"(f0) : "r"(hpk));
    asm("prmt.b32 %0, %1, 0, 0x3244;" : "=r"(f1) : "r"(hpk));
    float l0 = x0 - __uint_as_float(f0);
    float l1 = x1 - __uint_as_float(f1);
    asm("cvt.rn.bf16x2.f32 %0, %1, %2;" : "=r"(lp) : "f"(l1), "f"(l0));
    hp = hpk;
}
static __device__ __forceinline__ void split8_store(char* smem, u32 hoff, u32 loff,
                                                    u32 off, const float* v) {
    u32 h[4], l[4];
    splitpair(v[0], v[1], h[0], l[0]);
    splitpair(v[2], v[3], h[1], l[1]);
    splitpair(v[4], v[5], h[2], l[2]);
    splitpair(v[6], v[7], h[3], l[3]);
    *reinterpret_cast<uint4*>(smem + hoff + off) = make_uint4(h[0], h[1], h[2], h[3]);
    *reinterpret_cast<uint4*>(smem + loff + off) = make_uint4(l[0], l[1], l[2], l[3]);
}

__global__ __launch_bounds__(NTHREADS, 1)
void fa_ws2_kernel(const float* __restrict__ query,
                   const float* __restrict__ key,
                   const float* __restrict__ value,
                   const int*   __restrict__ q_start_loc,
                   const int*   __restrict__ q_seqlens,
                   float* __restrict__ out)
{
    extern __shared__ char smch[];
    const u32 sb = smem_u32(smch);

    const int qt   = blockIdx.x;
    const int h    = blockIdx.y;
    const int b    = blockIdx.z;
    const int tid  = threadIdx.x;
    const int wid  = tid >> 5;
    const int lane = tid & 31;

    const int q_start  = q_start_loc[b];
    const int q_len    = q_seqlens[b];
    const int kv_start = q_start;
    const int kv_len   = q_len;
    const int q0 = qt * BQ;
    if (q0 >= q_len) return;
    const int hk = h >> 2;

    // ---- Q tile: all threads cooperate; scaled, split hi/lo, swizzled ----
    for (int idx = tid; idx < BQ * 16; idx += NTHREADS) {
        const int row = idx >> 4;
        const int ch  = idx & 15;
        float v[8];
        #pragma unroll
        for (int i = 0; i < 8; i++) v[i] = 0.f;
        if (q0 + row < q_len) {
            const float* g = query + ((size_t)(q_start + q0 + row) * HEADS + h) * DHEAD + ch * 8;
            float4 a = *reinterpret_cast<const float4*>(g);
            float4 c = *reinterpret_cast<const float4*>(g + 4);
            v[0]=a.x; v[1]=a.y; v[2]=a.z; v[3]=a.w;
            v[4]=c.x; v[5]=c.y; v[6]=c.z; v[7]=c.w;
            #pragma unroll
            for (int i = 0; i < 8; i++) v[i] *= SCALE_OVER_CAP;
        }
        split8_store(smch, QH_OFF, QL_OFF, swadr(row, ch), v);
    }
    __syncthreads();

    int kj_lo = q0 - (WINDOW - 1); if (kj_lo < 0) kj_lo = 0;
    const int t0 = kj_lo >> 6;
    int t1 = (q0 + BQ - 1) >> 6;
    const int t1cap = (kv_len - 1) >> 6;
    if (t1 > t1cap) t1 = t1cap;

    if (wid >= 8) {
        // ================= PRODUCER (warps 8,9) =================
        const int ptid = (wid - 8) * 32 + lane;   // 0..63
        for (int kt = t0; kt <= t1; kt++) {
            const int bsel = (kt - t0) & 1;
            if (kt - t0 >= 2) BAR_SYNC(BAR_EMPTY0 + bsel);
            char* kvb = smch + KV_BASE + bsel * KVBUF;
            const int k0 = kt * BK;
            #pragma unroll 4
            for (int idx = ptid; idx < BK * 16; idx += 64) {
                const int row = idx >> 4;
                const int ch  = idx & 15;
                float kvv[8], vvv[8];
                #pragma unroll
                for (int i = 0; i < 8; i++) { kvv[i] = 0.f; vvv[i] = 0.f; }
                if (k0 + row < kv_len) {
                    const size_t base = ((size_t)(kv_start + k0 + row) * KVHEADS + hk) * DHEAD + ch * 8;
                    float4 a = *reinterpret_cast<const float4*>(key + base);
                    float4 c = *reinterpret_cast<const float4*>(key + base + 4);
                    kvv[0]=a.x; kvv[1]=a.y; kvv[2]=a.z; kvv[3]=a.w;
                    kvv[4]=c.x; kvv[5]=c.y; kvv[6]=c.z; kvv[7]=c.w;
                    a = *reinterpret_cast<const float4*>(value + base);
                    c = *reinterpret_cast<const float4*>(value + base + 4);
                    vvv[0]=a.x; vvv[1]=a.y; vvv[2]=a.z; vvv[3]=a.w;
                    vvv[4]=c.x; vvv[5]=c.y; vvv[6]=c.z; vvv[7]=c.w;
                }
                const u32 off = swadr(row, ch);
                split8_store(kvb, KH_R, KL_R, off, kvv);
                split8_store(kvb, VH_R, VL_R, off, vvv);
            }
            BAR_ARRIVE(BAR_FULL0 + bsel);
        }
        return;
    }

    // ================= CONSUMERS (warps 0..7) =================
    const int wrow = wid << 4;
    const int mi = lane >> 3, mr = lane & 7;
    const int arow = wrow + mr + ((mi & 1) << 3);
    const int acb  = mi >> 1;
    const int brow_off = ((mi >> 1) << 3) + mr;
    const int bcb  = mi & 1;
    const int vrow_off = ((mi & 1) << 3) + mr;
    const int vcb  = mi >> 1;

    const int qi0 = q0 + wrow + (lane >> 2);
    const int qi1 = qi0 + 8;

    float oacc[16][4];
    #pragma unroll
    for (int i = 0; i < 16; i++)
        #pragma unroll
        for (int j = 0; j < 4; j++) oacc[i][j] = 0.f;
    float lq0 = 0.f, lq1 = 0.f;

    for (int kt = t0; kt <= t1; kt++) {
        const int k0 = kt * BK;
        const int bsel = (kt - t0) & 1;
        BAR_SYNC(BAR_FULL0 + bsel);
        const u32 kvu = sb + KV_BASE + bsel * KVBUF;

        // ---- S = Q @ K^T : term-major, batched B-frags (reuse distance 8) ----
        float sacc[8][4];
        #pragma unroll
        for (int i = 0; i < 8; i++)
            #pragma unroll
            for (int j = 0; j < 4; j++) sacc[i][j] = 0.f;

        #pragma unroll
        for (int ks = 0; ks < 8; ks++) {
            u32 ah[4], al[4];
            const u32 aoff = swadr(arow, 2 * ks + acb);
            ldsm4(sb + QH_OFF + aoff, ah);
            ldsm4(sb + QL_OFF + aoff, al);
            u32 bh[4][4], bl[4][4];
            #pragma unroll
            for (int ntp = 0; ntp < 4; ntp++) {
                const u32 boff = swadr(16 * ntp + brow_off, 2 * ks + bcb);
                ldsm4(kvu + KH_R + boff, bh[ntp]);
                ldsm4(kvu + KL_R + boff, bl[ntp]);
            }
            #pragma unroll
            for (int ntp = 0; ntp < 4; ntp++) {
                mma_bf16(sacc[2*ntp],   ah, &bh[ntp][0]);
                mma_bf16(sacc[2*ntp+1], ah, &bh[ntp][2]);
            }
            #pragma unroll
            for (int ntp = 0; ntp < 4; ntp++) {
                mma_bf16(sacc[2*ntp],   al, &bh[ntp][0]);
                mma_bf16(sacc[2*ntp+1], al, &bh[ntp][2]);
            }
            #pragma unroll
            for (int ntp = 0; ntp < 4; ntp++) {
                mma_bf16(sacc[2*ntp],   ah, &bl[ntp][0]);
                mma_bf16(sacc[2*ntp+1], ah, &bl[ntp][2]);
            }
        }

        // ---- epilogue: p = exp(30*tanh(x) - 30); interior tiles skip masks ----
        const bool full = (k0 + BK - 1 <= q0 + wrow)
                       && ((q0 + wrow + 15 - k0) < WINDOW)
                       && (k0 + BK <= kv_len);
        u32 pah[4][4], pal[4][4];
        #pragma unroll
        for (int nt = 0; nt < 8; nt++) {
            const int kj = k0 + nt * 8 + ((lane & 3) << 1);
            float p[4];
            #pragma unroll
            for (int c = 0; c < 4; c++) {
                const float x = sacc[nt][c];
                const float x2 = x * x;
                float th = x * fmaf(x2, fmaf(x2, 0.13333334f, -0.33333334f), 1.0f);
                if (x2 > 0.0625f) {            // |x| > 0.25 : rare (x ~ N(0,1/900))
                    const float e = exp2f(x * TWO_LOG2E);
                    th = 1.f - __fdividef(2.f, e + 1.f);
                }
                p[c] = exp2f(fmaf(th, CAP_LOG2E, -CAP_LOG2E));
            }
            if (!full) {
                #pragma unroll
                for (int c = 0; c < 4; c++) {
                    const int qi = (c < 2) ? qi0 : qi1;
                    const int kc = kj + (c & 1);
                    const bool ok = ((u32)(qi - kc) < WINDOW) && (kc < kv_len);
                    p[c] = ok ? p[c] : 0.f;
                }
            }
            lq0 += p[0] + p[1];
            lq1 += p[2] + p[3];
            const int ks2 = nt >> 1;
            const int o   = (nt & 1) << 1;
            splitpair(p[0], p[1], pah[ks2][o],     pal[ks2][o]);
            splitpair(p[2], p[3], pah[ks2][o + 1], pal[ks2][o + 1]);
        }

        // ---- O += P @ V : term-major in dtp groups of 4 (reuse distance 8) ----
        #pragma unroll
        for (int ks2 = 0; ks2 < 4; ks2++) {
            #pragma unroll
            for (int g = 0; g < 2; g++) {
                u32 vh[4][4], vl[4][4];
                #pragma unroll
                for (int t = 0; t < 4; t++) {
                    const int dtp = g * 4 + t;
                    const u32 voff = swadr(16 * ks2 + vrow_off, 2 * dtp + vcb);
                    ldsm4t(kvu + VH_R + voff, vh[t]);
                    ldsm4t(kvu + VL_R + voff, vl[t]);
                }
                #pragma unroll
                for (int t = 0; t < 4; t++) {
                    const int dtp = g * 4 + t;
                    mma_bf16(oacc[2*dtp],   pah[ks2], &vh[t][0]);
                    mma_bf16(oacc[2*dtp+1], pah[ks2], &vh[t][2]);
                }
                #pragma unroll
                for (int t = 0; t < 4; t++) {
                    const int dtp = g * 4 + t;
                    mma_bf16(oacc[2*dtp],   pal[ks2], &vh[t][0]);
                    mma_bf16(oacc[2*dtp+1], pal[ks2], &vh[t][2]);
                }
                #pragma unroll
                for (int t = 0; t < 4; t++) {
                    const int dtp = g * 4 + t;
                    mma_bf16(oacc[2*dtp],   pah[ks2], &vl[t][0]);
                    mma_bf16(oacc[2*dtp+1], pah[ks2], &vl[t][2]);
                }
            }
        }
        BAR_ARRIVE(BAR_EMPTY0 + bsel);
    }

    // ---- reduce l across 4 lanes per row, normalize, store ----
    lq0 += __shfl_xor_sync(0xffffffffu, lq0, 1);
    lq0 += __shfl_xor_sync(0xffffffffu, lq0, 2);
    lq1 += __shfl_xor_sync(0xffffffffu, lq1, 1);
    lq1 += __shfl_xor_sync(0xffffffffu, lq1, 2);
    const float inv0 = __fdividef(1.f, lq0);
    const float inv1 = __fdividef(1.f, lq1);

    const int colb = (lane & 3) << 1;
    if (qi0 < q_len) {
        float* g = out + ((size_t)(q_start + qi0) * HEADS + h) * DHEAD + colb;
        #pragma unroll
        for (int nt = 0; nt < 16; nt++)
            *reinterpret_cast<float2*>(g + nt * 8) =
                make_float2(oacc[nt][0] * inv0, oacc[nt][1] * inv0);
    }
    if (qi1 < q_len) {
        float* g = out + ((size_t)(q_start + qi1) * HEADS + h) * DHEAD + colb;
        #pragma unroll
        for (int nt = 0; nt < 16; nt++)
            *reinterpret_cast<float2*>(g + nt * 8) =
                make_float2(oacc[nt][2] * inv1, oacc[nt][3] * inv1);
    }
}

extern "C" void kernel_launch(void* const* d_in, const int* in_sizes, int n_in,
                              void* d_out, int out_size)
{
    const float* query = (const float*)d_in[0];
    const float* key   = (const float*)d_in[1];
    const float* value = (const float*)d_in[2];
    const int* q_start_loc = (const int*)d_in[3];
    const int* q_seqlens   = (const int*)d_in[4];
    float* out = (float*)d_out;

    const int total  = in_sizes[0] / (HEADS * DHEAD);
    const int batch  = in_sizes[3];
    const int seqlen = total / batch;
    const int n_qtiles = (seqlen + BQ - 1) / BQ;

    cudaFuncSetAttribute(fa_ws2_kernel,
                         cudaFuncAttributeMaxDynamicSharedMemorySize, SMEM_TOTAL);

    dim3 grid(n_qtiles, HEADS, batch);
    fa_ws2_kernel<<<grid, NTHREADS, SMEM_TOTAL>>>(
        query, key, value, q_start_loc, q_seqlens, out);
}

// round 8
// speedup vs baseline: 1.7254x; 1.7254x over previous
#include <cuda_runtime.h>
#include <cuda_fp16.h>

// query [TOTAL,16,128] f32, key/value [TOTAL,4,128] f32, q_start_loc [B] i32,
// q_seqlens [B] i32 -> out [TOTAL,16,128] f32.
#define HEADS   16
#define KVHEADS 4
#define DHEAD   128
#define WINDOW  1024
#define BQ 128
#define BK 64
#define NTHREADS 320          // 8 consumer warps + 2 producer warps

#define SCALE   0.08838834764831845f            // 128^-0.5
#define INV30   0.033333333333333333f
#define T2L30   0.09617966939259756f            // 2*log2(e)/30
#define LOG2E   1.4426950408889634f
#define M_INIT  (-1.0e4f)                       // below any real score (|s|<30)

// smem: fp16 tiles, rows of 128 fp16 (256B = 16 chunks of 16B), chunk-XOR swizzle.
#define Q_OFF   0          // [128][128] fp16 : 32768
#define KV_BASE 32768      // two 32KB buffers: {K,V} each 16384
#define KVBUF   32768
#define K_R 0
#define V_R 16384
#define SMEM_TOTAL 98304

#define BAR_FULL0 1
#define BAR_FULL1 2
#define BAR_EMPTY0 3
#define BAR_EMPTY1 4
#define BAR_SYNC(id)   asm volatile("bar.sync %0, %1;"   :: "r"(id), "r"(NTHREADS) : "memory")
#define BAR_ARRIVE(id) asm volatile("bar.arrive %0, %1;" :: "r"(id), "r"(NTHREADS) : "memory")

typedef unsigned int u32;

static __device__ __forceinline__ u32 smem_u32(const void* p) {
    u32 a;
    asm("{ .reg .u64 t; cvta.to.shared.u64 t, %1; cvt.u32.u64 %0, t; }"
        : "=r"(a) : "l"(p));
    return a;
}
static __device__ __forceinline__ u32 swadr(int row, int chunk) {
    return (u32)((row << 8) + ((chunk ^ (row & 7)) << 4));
}
static __device__ __forceinline__ void ldsm4(u32 addr, u32 r[4]) {
    asm volatile("ldmatrix.sync.aligned.m8n8.x4.shared.b16 {%0,%1,%2,%3}, [%4];"
        : "=r"(r[0]), "=r"(r[1]), "=r"(r[2]), "=r"(r[3]) : "r"(addr));
}
static __device__ __forceinline__ void ldsm4t(u32 addr, u32 r[4]) {
    asm volatile("ldmatrix.sync.aligned.m8n8.x4.trans.shared.b16 {%0,%1,%2,%3}, [%4];"
        : "=r"(r[0]), "=r"(r[1]), "=r"(r[2]), "=r"(r[3]) : "r"(addr));
}
static __device__ __forceinline__ void mma_f16(float c[4], const u32 a[4], const u32 b[2]) {
    asm volatile(
        "mma.sync.aligned.m16n8k16.row.col.f32.f16.f16.f32 "
        "{%0,%1,%2,%3}, {%4,%5,%6,%7}, {%8,%9}, {%0,%1,%2,%3};"
        : "+f"(c[0]), "+f"(c[1]), "+f"(c[2]), "+f"(c[3])
        : "r"(a[0]), "r"(a[1]), "r"(a[2]), "r"(a[3]), "r"(b[0]), "r"(b[1]));
}
// pack (x0,x1) -> fp16x2 (low half = x0)
static __device__ __forceinline__ u32 pack_h2(float x0, float x1) {
    u32 r;
    asm("cvt.rn.f16x2.f32 %0, %1, %2;" : "=r"(r) : "f"(x1), "f"(x0));
    return r;
}
// convert 8 floats -> one 16B fp16 chunk
static __device__ __forceinline__ void h8_store(char* smem, u32 off, const float* v) {
    *reinterpret_cast<uint4*>(smem + off) =
        make_uint4(pack_h2(v[0], v[1]), pack_h2(v[2], v[3]),
                   pack_h2(v[4], v[5]), pack_h2(v[6], v[7]));
}

__global__ __launch_bounds__(NTHREADS, 1)
void fa_fp16_kernel(const float* __restrict__ query,
                    const float* __restrict__ key,
                    const float* __restrict__ value,
                    const int*   __restrict__ q_start_loc,
                    const int*   __restrict__ q_seqlens,
                    float* __restrict__ out)
{
    extern __shared__ char smch[];
    const u32 sb = smem_u32(smch);

    const int qt   = blockIdx.x;
    const int h    = blockIdx.y;
    const int b    = blockIdx.z;
    const int tid  = threadIdx.x;
    const int wid  = tid >> 5;
    const int lane = tid & 31;

    const int q_start  = q_start_loc[b];
    const int q_len    = q_seqlens[b];
    const int kv_start = q_start;
    const int kv_len   = q_len;
    const int q0 = qt * BQ;
    if (q0 >= q_len) return;
    const int hk = h >> 2;

    // ---- Q tile: scaled by 1/sqrt(D), fp16, swizzled ----
    for (int idx = tid; idx < BQ * 16; idx += NTHREADS) {
        const int row = idx >> 4;
        const int ch  = idx & 15;
        float v[8];
        #pragma unroll
        for (int i = 0; i < 8; i++) v[i] = 0.f;
        if (q0 + row < q_len) {
            const float* g = query + ((size_t)(q_start + q0 + row) * HEADS + h) * DHEAD + ch * 8;
            float4 a = *reinterpret_cast<const float4*>(g);
            float4 c = *reinterpret_cast<const float4*>(g + 4);
            v[0]=a.x*SCALE; v[1]=a.y*SCALE; v[2]=a.z*SCALE; v[3]=a.w*SCALE;
            v[4]=c.x*SCALE; v[5]=c.y*SCALE; v[6]=c.z*SCALE; v[7]=c.w*SCALE;
        }
        h8_store(smch, Q_OFF + swadr(row, ch), v);
    }
    __syncthreads();

    int kj_lo = q0 - (WINDOW - 1); if (kj_lo < 0) kj_lo = 0;
    const int t0 = kj_lo >> 6;
    int t1 = (q0 + BQ - 1) >> 6;
    const int t1cap = (kv_len - 1) >> 6;
    if (t1 > t1cap) t1 = t1cap;

    if (wid >= 8) {
        // ================= PRODUCER (warps 8,9) =================
        const int ptid = (wid - 8) * 32 + lane;   // 0..63
        for (int kt = t0; kt <= t1; kt++) {
            const int bsel = (kt - t0) & 1;
            if (kt - t0 >= 2) BAR_SYNC(BAR_EMPTY0 + bsel);
            char* kvb = smch + KV_BASE + bsel * KVBUF;
            const int k0 = kt * BK;
            #pragma unroll 4
            for (int idx = ptid; idx < BK * 16; idx += 64) {
                const int row = idx >> 4;
                const int ch  = idx & 15;
                float kvv[8], vvv[8];
                #pragma unroll
                for (int i = 0; i < 8; i++) { kvv[i] = 0.f; vvv[i] = 0.f; }
                if (k0 + row < kv_len) {
                    const size_t base = ((size_t)(kv_start + k0 + row) * KVHEADS + hk) * DHEAD + ch * 8;
                    float4 a = *reinterpret_cast<const float4*>(key + base);
                    float4 c = *reinterpret_cast<const float4*>(key + base + 4);
                    kvv[0]=a.x; kvv[1]=a.y; kvv[2]=a.z; kvv[3]=a.w;
                    kvv[4]=c.x; kvv[5]=c.y; kvv[6]=c.z; kvv[7]=c.w;
                    a = *reinterpret_cast<const float4*>(value + base);
                    c = *reinterpret_cast<const float4*>(value + base + 4);
                    vvv[0]=a.x; vvv[1]=a.y; vvv[2]=a.z; vvv[3]=a.w;
                    vvv[4]=c.x; vvv[5]=c.y; vvv[6]=c.z; vvv[7]=c.w;
                }
                const u32 off = swadr(row, ch);
                h8_store(kvb, K_R + off, kvv);
                h8_store(kvb, V_R + off, vvv);
            }
            BAR_ARRIVE(BAR_FULL0 + bsel);
        }
        return;
    }

    // ================= CONSUMERS (warps 0..7) =================
    const int wrow = wid << 4;
    const int mi = lane >> 3, mr = lane & 7;
    const int arow = wrow + mr + ((mi & 1) << 3);
    const int acb  = mi >> 1;
    const int brow_off = ((mi >> 1) << 3) + mr;
    const int bcb  = mi & 1;
    const int vrow_off = ((mi & 1) << 3) + mr;
    const int vcb  = mi >> 1;

    const int qi0 = q0 + wrow + (lane >> 2);
    const int qi1 = qi0 + 8;

    float oacc[16][4];
    #pragma unroll
    for (int i = 0; i < 16; i++)
        #pragma unroll
        for (int j = 0; j < 4; j++) oacc[i][j] = 0.f;
    float lq0 = 0.f, lq1 = 0.f;
    float mrow0 = M_INIT, mrow1 = M_INIT;

    for (int kt = t0; kt <= t1; kt++) {
        const int k0 = kt * BK;
        const int bsel = (kt - t0) & 1;
        BAR_SYNC(BAR_FULL0 + bsel);
        const u32 kvu = sb + KV_BASE + bsel * KVBUF;

        // per-warp tile skip: this warp's 16 rows vs tile keys
        const bool active = (k0 <= q0 + wrow + 15)
                         && (k0 + BK - 1 >= q0 + wrow - (WINDOW - 1));
        if (active) {
            // ---- S = Q @ K^T (single fp16, fp32 accum); sacc = raw logit ----
            float sacc[8][4];
            #pragma unroll
            for (int i = 0; i < 8; i++)
                #pragma unroll
                for (int j = 0; j < 4; j++) sacc[i][j] = 0.f;

            #pragma unroll
            for (int ks = 0; ks < 8; ks++) {
                u32 aq[4];
                ldsm4(sb + Q_OFF + swadr(arow, 2 * ks + acb), aq);
                #pragma unroll
                for (int ntp = 0; ntp < 4; ntp++) {
                    u32 bk[4];
                    ldsm4(kvu + K_R + swadr(16 * ntp + brow_off, 2 * ks + bcb), bk);
                    mma_f16(sacc[2*ntp],   aq, &bk[0]);
                    mma_f16(sacc[2*ntp+1], aq, &bk[2]);
                }
            }

            // ---- pass 1: softcap s = 30*tanh(d/30), mask, tile row max ----
            const bool full = (k0 + BK - 1 <= q0 + wrow)
                           && ((q0 + wrow + 15 - k0) < WINDOW)
                           && (k0 + BK <= kv_len);
            float tm0 = -1e30f, tm1 = -1e30f;
            #pragma unroll
            for (int nt = 0; nt < 8; nt++) {
                const int kj = k0 + nt * 8 + ((lane & 3) << 1);
                #pragma unroll
                for (int c = 0; c < 4; c++) {
                    const float d = sacc[nt][c];
                    const float t = d * INV30;
                    const float x2 = t * t;
                    float s = d * fmaf(x2, fmaf(x2, 0.13333334f, -0.33333334f), 1.0f);
                    if (x2 > 0.0625f) {            // |d| > 7.5 : rare (d ~ N(0,1))
                        const float e = exp2f(d * T2L30);
                        s = 30.f - __fdividef(60.f, e + 1.f);
                    }
                    if (!full) {
                        const int qi = (c < 2) ? qi0 : qi1;
                        const int kc = kj + (c & 1);
                        const bool ok = ((u32)(qi - kc) < WINDOW) && (kc < kv_len);
                        s = ok ? s : -1e30f;
                    }
                    sacc[nt][c] = s;
                    if (c < 2) tm0 = fmaxf(tm0, s); else tm1 = fmaxf(tm1, s);
                }
            }
            tm0 = fmaxf(tm0, __shfl_xor_sync(0xffffffffu, tm0, 1));
            tm0 = fmaxf(tm0, __shfl_xor_sync(0xffffffffu, tm0, 2));
            tm1 = fmaxf(tm1, __shfl_xor_sync(0xffffffffu, tm1, 1));
            tm1 = fmaxf(tm1, __shfl_xor_sync(0xffffffffu, tm1, 2));

            const float mnew0 = fmaxf(mrow0, tm0);
            const float mnew1 = fmaxf(mrow1, tm1);
            const float alpha0 = exp2f((mrow0 - mnew0) * LOG2E);
            const float alpha1 = exp2f((mrow1 - mnew1) * LOG2E);
            mrow0 = mnew0; mrow1 = mnew1;
            lq0 *= alpha0; lq1 *= alpha1;
            #pragma unroll
            for (int i = 0; i < 16; i++) {
                oacc[i][0] *= alpha0; oacc[i][1] *= alpha0;
                oacc[i][2] *= alpha1; oacc[i][3] *= alpha1;
            }

            // ---- pass 2: p = exp(s - m), fp16 A-frags for PV ----
            u32 pa[4][4];
            #pragma unroll
            for (int nt = 0; nt < 8; nt++) {
                const float p0 = exp2f((sacc[nt][0] - mnew0) * LOG2E);
                const float p1 = exp2f((sacc[nt][1] - mnew0) * LOG2E);
                const float p2 = exp2f((sacc[nt][2] - mnew1) * LOG2E);
                const float p3 = exp2f((sacc[nt][3] - mnew1) * LOG2E);
                lq0 += p0 + p1;
                lq1 += p2 + p3;
                const int ks2 = nt >> 1;
                const int o   = (nt & 1) << 1;
                pa[ks2][o]     = pack_h2(p0, p1);
                pa[ks2][o + 1] = pack_h2(p2, p3);
            }

            // ---- O += P @ V (single fp16), V via ldmatrix.trans ----
            #pragma unroll
            for (int ks2 = 0; ks2 < 4; ks2++) {
                #pragma unroll
                for (int dtp = 0; dtp < 8; dtp++) {
                    u32 bv[4];
                    ldsm4t(kvu + V_R + swadr(16 * ks2 + vrow_off, 2 * dtp + vcb), bv);
                    mma_f16(oacc[2*dtp],   pa[ks2], &bv[0]);
                    mma_f16(oacc[2*dtp+1], pa[ks2], &bv[2]);
                }
            }
        }
        BAR_ARRIVE(BAR_EMPTY0 + bsel);
    }

    // ---- reduce l across 4 lanes per row, normalize, store ----
    lq0 += __shfl_xor_sync(0xffffffffu, lq0, 1);
    lq0 += __shfl_xor_sync(0xffffffffu, lq0, 2);
    lq1 += __shfl_xor_sync(0xffffffffu, lq1, 1);
    lq1 += __shfl_xor_sync(0xffffffffu, lq1, 2);
    const float inv0 = __fdividef(1.f, lq0);
    const float inv1 = __fdividef(1.f, lq1);

    const int colb = (lane & 3) << 1;
    if (qi0 < q_len) {
        float* g = out + ((size_t)(q_start + qi0) * HEADS + h) * DHEAD + colb;
        #pragma unroll
        for (int nt = 0; nt < 16; nt++)
            *reinterpret_cast<float2*>(g + nt * 8) =
                make_float2(oacc[nt][0] * inv0, oacc[nt][1] * inv0);
    }
    if (qi1 < q_len) {
        float* g = out + ((size_t)(q_start + qi1) * HEADS + h) * DHEAD + colb;
        #pragma unroll
        for (int nt = 0; nt < 16; nt++)
            *reinterpret_cast<float2*>(g + nt * 8) =
                make_float2(oacc[nt][2] * inv1, oacc[nt][3] * inv1);
    }
}

extern "C" void kernel_launch(void* const* d_in, const int* in_sizes, int n_in,
                              void* d_out, int out_size)
{
    const float* query = (const float*)d_in[0];
    const float* key   = (const float*)d_in[1];
    const float* value = (const float*)d_in[2];
    const int* q_start_loc = (const int*)d_in[3];
    const int* q_seqlens   = (const int*)d_in[4];
    float* out = (float*)d_out;

    const int total  = in_sizes[0] / (HEADS * DHEAD);
    const int batch  = in_sizes[3];
    const int seqlen = total / batch;
    const int n_qtiles = (seqlen + BQ - 1) / BQ;

    cudaFuncSetAttribute(fa_fp16_kernel,
                         cudaFuncAttributeMaxDynamicSharedMemorySize, SMEM_TOTAL);

    dim3 grid(n_qtiles, HEADS, batch);
    fa_fp16_kernel<<<grid, NTHREADS, SMEM_TOTAL>>>(
        query, key, value, q_start_loc, q_seqlens, out);
}